// round 9
// baseline (speedup 1.0000x reference)
#include <cuda_runtime.h>
#include <cuda_fp16.h>
#include <cstdint>

#define N_USERS 100000
#define N_ITEMS 50000
#define N_NODES (N_USERS + N_ITEMS)   // 150000
#define D 64
#define DH4 (D / 8)                   // 8 uint4 (8 halves each) per row
#define MAX_E 4000000

#define SCAN_BLK  1024
#define SCAN_TILE (SCAN_BLK * 4)                           // 4096
#define SCAN_NB   ((N_ITEMS + SCAN_TILE - 1) / SCAN_TILE)  // 13

// ---------------- static device scratch -------------------------------------
// INVARIANT: g_count == 0 at entry of every kernel_launch call.
// (zero at load; scanA_kernel restores zeros after consuming the counts)
__device__ int   g_count[(N_ITEMS + 3) & ~3];
__device__ int   g_wcur [N_ITEMS];
__device__ int   g_ptr  [N_NODES + 1];
__device__ int   g_bsum [SCAN_NB];
__device__ int   g_edge [MAX_E];                       // 4B neighbor index only
__device__ uint4 g_t0   [(size_t)N_NODES * DH4];       // inv*emb (fp16)
__device__ uint4 g_t1   [(size_t)N_NODES * DH4];       // inv*c1  (fp16)
__device__ uint4 g_t2   [(size_t)N_NODES * DH4];       // inv*c2  (fp16)

// ---------------- step 1: user ptrs + edge pack + item histogram (fused) ----
// Only rows/cols[0:E2] are read; item half of inputs is a role-swap.
__global__ void build1_kernel(const int* __restrict__ rows,
                              const int* __restrict__ cols, int E2) {
    int idx = blockIdx.x * blockDim.x + threadIdx.x;
    if (idx < E2) {
        int c = cols[idx];                 // item node id (item + N_USERS)
        g_edge[idx] = c;
        atomicAdd(&g_count[c - N_USERS], 1);
    }
    // user CSR ptrs via binary search over sorted rows[0:E2]
    if (idx < N_USERS) {
        int lo = 0, hi = E2;
        while (lo < hi) {
            int m = (lo + hi) >> 1;
            if (rows[m] < idx) lo = m + 1; else hi = m;
        }
        g_ptr[idx] = lo;
    }
}

// ---------------- step 2a: per-block local exclusive scan (+count reset) ----
__global__ void scanA_kernel() {
    __shared__ int wsum[32];
    const int tid  = threadIdx.x;
    const int lane = tid & 31;
    const int wid  = tid >> 5;
    int base = blockIdx.x * SCAN_TILE + tid * 4;

    int4 v = make_int4(0, 0, 0, 0);
    if (base < N_ITEMS) {
        v = *(const int4*)&g_count[base];
        *(int4*)&g_count[base] = make_int4(0, 0, 0, 0);   // restore invariant
    }
    if (base >= N_ITEMS)     v.x = 0;
    if (base + 1 >= N_ITEMS) v.y = 0;
    if (base + 2 >= N_ITEMS) v.z = 0;
    if (base + 3 >= N_ITEMS) v.w = 0;

    int t = v.x + v.y + v.z + v.w;
    int x = t;
    #pragma unroll
    for (int o = 1; o < 32; o <<= 1) {
        int y = __shfl_up_sync(0xffffffffu, x, o);
        if (lane >= o) x += y;
    }
    if (lane == 31) wsum[wid] = x;
    __syncthreads();
    if (wid == 0) {
        int w = wsum[lane];
        int xs = w;
        #pragma unroll
        for (int o = 1; o < 32; o <<= 1) {
            int y = __shfl_up_sync(0xffffffffu, xs, o);
            if (lane >= o) xs += y;
        }
        wsum[lane] = xs - w;
    }
    __syncthreads();
    int excl = (x - t) + wsum[wid];

    int e0 = excl;
    int e1 = e0 + v.x;
    int e2 = e1 + v.y;
    int e3 = e2 + v.z;
    if (base < N_ITEMS) {
        int lim = N_ITEMS - base;
        int* p = &g_ptr[N_USERS + base];
        if (lim > 0) p[0] = e0;
        if (lim > 1) p[1] = e1;
        if (lim > 2) p[2] = e2;
        if (lim > 3) p[3] = e3;
    }
    if (tid == SCAN_BLK - 1) g_bsum[blockIdx.x] = e3 + v.w;
}

// ---------------- step 2b: apply tile offsets --------------------------------
__global__ void scanC_kernel(int E2) {
    int gid = blockIdx.x * blockDim.x + threadIdx.x;
    int i4 = gid * 4;
    if (gid == 0) {
        int tot = E2;
        #pragma unroll
        for (int j = 0; j < SCAN_NB; j++) tot += g_bsum[j];
        g_ptr[N_NODES] = tot;              // == E
    }
    if (i4 >= N_ITEMS) return;
    int tile = i4 / SCAN_TILE;
    int off = E2;
    for (int j = 0; j < tile; j++) off += g_bsum[j];
    int lim = N_ITEMS - i4;
    int* p = &g_ptr[N_USERS + i4];
    #pragma unroll
    for (int k = 0; k < 4; k++) {
        if (k < lim) {
            int val = p[k] + off;
            p[k] = val;
            g_wcur[i4 + k] = val;
        }
    }
}

// ---------------- step 3: scatter item-half edges + scaled fp16 convert -----
__global__ void scatter_convert_kernel(const int* __restrict__ rows,
                                       const float* __restrict__ embeds,
                                       int E2) {
    int idx = blockIdx.x * blockDim.x + threadIdx.x;

    if (idx < E2) {
        int c = g_edge[idx];                           // item node id
        int p = atomicAdd(&g_wcur[c - N_USERS], 1);    // p >= E2: no race w/ reads
        g_edge[p] = rows[idx];                         // user node id
    }

    if (idx < N_NODES * DH4) {
        int node = idx >> 3;
        int deg  = g_ptr[node + 1] - g_ptr[node];
        float inv = (deg > 0) ? rsqrtf((float)deg) : 0.f;
        const float4* e4 = (const float4*)embeds;
        float4 f0 = e4[2 * idx];
        float4 f1 = e4[2 * idx + 1];
        __half2 h0 = __floats2half2_rn(inv * f0.x, inv * f0.y);
        __half2 h1 = __floats2half2_rn(inv * f0.z, inv * f0.w);
        __half2 h2 = __floats2half2_rn(inv * f1.x, inv * f1.y);
        __half2 h3 = __floats2half2_rn(inv * f1.z, inv * f1.w);
        uint4 u;
        u.x = *(const unsigned*)&h0;
        u.y = *(const unsigned*)&h1;
        u.z = *(const unsigned*)&h2;
        u.w = *(const unsigned*)&h3;
        g_t0[idx] = u;
    }
}

// ---------------- SpMM helpers -----------------------------------------------
__device__ __forceinline__ void add8(float* s, uint4 x) {
    float2 f0 = __half22float2(*(const __half2*)&x.x);
    float2 f1 = __half22float2(*(const __half2*)&x.y);
    float2 f2 = __half22float2(*(const __half2*)&x.z);
    float2 f3 = __half22float2(*(const __half2*)&x.w);
    s[0] += f0.x; s[1] += f0.y;
    s[2] += f1.x; s[3] += f1.y;
    s[4] += f2.x; s[5] += f2.y;
    s[6] += f3.x; s[7] += f3.y;
}

__device__ __forceinline__ uint4 pack8s(const float* s, float w) {
    __half2 h0 = __floats2half2_rn(w * s[0], w * s[1]);
    __half2 h1 = __floats2half2_rn(w * s[2], w * s[3]);
    __half2 h2 = __floats2half2_rn(w * s[4], w * s[5]);
    __half2 h3 = __floats2half2_rn(w * s[6], w * s[7]);
    uint4 u;
    u.x = *(const unsigned*)&h0;
    u.y = *(const unsigned*)&h1;
    u.z = *(const unsigned*)&h2;
    u.w = *(const unsigned*)&h3;
    return u;
}

// warp-collective edge sum: lane = eoff(0..3) * 8 + ln(0..7)
// after loop, butterfly-reduce across eoff; lanes 0-7 hold the full sums.
__device__ __forceinline__ void warp_edge_sum(const uint4* __restrict__ src,
                                              int beg, int end,
                                              int eoff, int ln, float* s) {
    int e = beg + eoff;
    // 2-way unroll: 8 independent gathers in flight per warp
    for (; e + 4 < end; e += 8) {
        int ca = g_edge[e];
        int cb = g_edge[e + 4];
        uint4 xa = src[(size_t)ca * DH4 + ln];
        uint4 xb = src[(size_t)cb * DH4 + ln];
        add8(s, xa);
        add8(s, xb);
    }
    if (e < end) {
        uint4 xa = src[(size_t)g_edge[e] * DH4 + ln];
        add8(s, xa);
    }
    #pragma unroll
    for (int k = 0; k < 8; k++) {
        s[k] += __shfl_xor_sync(0xffffffffu, s[k], 8);
        s[k] += __shfl_xor_sync(0xffffffffu, s[k], 16);
    }
}

// ---------------- SpMM: t_{k+1}[n] = (sum_{c in N(n)} t_k[c]) / deg(n) ------
template <int LAYER>   // 0: t0 -> t1,  1: t1 -> t2
__global__ void spmm_kernel() {
    int node = blockIdx.x * (blockDim.x >> 5) + (threadIdx.x >> 5);
    int lane = threadIdx.x & 31;
    int eoff = lane >> 3;
    int ln   = lane & 7;
    if (node >= N_NODES) return;

    const uint4* __restrict__ src = (LAYER == 0) ? g_t0 : g_t1;
    uint4* __restrict__ dst       = (LAYER == 0) ? g_t1 : g_t2;

    int beg = g_ptr[node];
    int end = g_ptr[node + 1];

    float s[8] = {0.f, 0.f, 0.f, 0.f, 0.f, 0.f, 0.f, 0.f};
    warp_edge_sum(src, beg, end, eoff, ln, s);

    if (eoff == 0) {
        int deg = end - beg;
        float w = (deg > 0) ? (1.f / (float)deg) : 0.f;
        dst[(size_t)node * DH4 + ln] = pack8s(s, w);
    }
}

// ---------------- fused layer-3 SpMM + final gather -------------------------
// out = 0.25 * ( emb[n] + (t1[n]+t2[n])*sqrt(deg) + rsqrt(deg)*sum_c t2[c] )
__global__ void final_kernel(const float* __restrict__ embeds,
                             const int* __restrict__ users,
                             const int* __restrict__ pos,
                             const int* __restrict__ neg,
                             float4* __restrict__ out, int B) {
    int row  = blockIdx.x * (blockDim.x >> 5) + (threadIdx.x >> 5);
    int lane = threadIdx.x & 31;
    int eoff = lane >> 3;
    int ln   = lane & 7;
    if (row >= 3 * B) return;
    int grp = row / B;
    int r   = row - grp * B;
    int n;
    if (grp == 0)      n = users[r];
    else if (grp == 1) n = pos[r] + N_USERS;
    else               n = neg[r] + N_USERS;

    int beg = g_ptr[n];
    int end = g_ptr[n + 1];
    float s[8] = {0.f, 0.f, 0.f, 0.f, 0.f, 0.f, 0.f, 0.f};
    warp_edge_sum(g_t2, beg, end, eoff, ln, s);
    if (eoff != 0) return;

    int deg = end - beg;
    float sq  = (deg > 0) ? sqrtf((float)deg)  : 0.f;
    float inv = (deg > 0) ? rsqrtf((float)deg) : 0.f;

    size_t ni = (size_t)n * DH4 + ln;
    const float4* e4 = (const float4*)embeds;
    float4 f0 = e4[2 * ni];
    float4 f1 = e4[2 * ni + 1];
    uint4 u1 = g_t1[ni];
    uint4 u2 = g_t2[ni];

    float tf[8];
    {
        float2 a0 = __half22float2(*(const __half2*)&u1.x);
        float2 a1 = __half22float2(*(const __half2*)&u1.y);
        float2 a2 = __half22float2(*(const __half2*)&u1.z);
        float2 a3 = __half22float2(*(const __half2*)&u1.w);
        float2 b0 = __half22float2(*(const __half2*)&u2.x);
        float2 b1 = __half22float2(*(const __half2*)&u2.y);
        float2 b2 = __half22float2(*(const __half2*)&u2.z);
        float2 b3 = __half22float2(*(const __half2*)&u2.w);
        tf[0] = a0.x + b0.x; tf[1] = a0.y + b0.y;
        tf[2] = a1.x + b1.x; tf[3] = a1.y + b1.y;
        tf[4] = a2.x + b2.x; tf[5] = a2.y + b2.y;
        tf[6] = a3.x + b3.x; tf[7] = a3.y + b3.y;
    }

    float4 o0, o1;
    o0.x = 0.25f * (f0.x + tf[0] * sq + s[0] * inv);
    o0.y = 0.25f * (f0.y + tf[1] * sq + s[1] * inv);
    o0.z = 0.25f * (f0.z + tf[2] * sq + s[2] * inv);
    o0.w = 0.25f * (f0.w + tf[3] * sq + s[3] * inv);
    o1.x = 0.25f * (f1.x + tf[4] * sq + s[4] * inv);
    o1.y = 0.25f * (f1.y + tf[5] * sq + s[5] * inv);
    o1.z = 0.25f * (f1.z + tf[6] * sq + s[6] * inv);
    o1.w = 0.25f * (f1.w + tf[7] * sq + s[7] * inv);
    size_t oi = (size_t)row * DH4 + ln;
    out[2 * oi]     = o0;
    out[2 * oi + 1] = o1;
}

// ---------------- launch -----------------------------------------------------
extern "C" void kernel_launch(void* const* d_in, const int* in_sizes, int n_in,
                              void* d_out, int out_size) {
    const float* embeds = (const float*)d_in[0];
    const int*   rows   = (const int*)d_in[2];
    const int*   cols   = (const int*)d_in[3];
    const int*   users  = (const int*)d_in[4];
    const int*   pos    = (const int*)d_in[5];
    const int*   neg    = (const int*)d_in[6];
    const int E  = in_sizes[1];
    const int E2 = E >> 1;
    const int B  = in_sizes[4];
    float4* out = (float4*)d_out;

    build1_kernel<<<(E2 + 255) / 256, 256>>>(rows, cols, E2);
    scanA_kernel<<<SCAN_NB, SCAN_BLK>>>();
    scanC_kernel<<<(N_ITEMS / 4 + 256) / 256, 256>>>(E2);

    int sc_threads = (E2 > N_NODES * DH4) ? E2 : N_NODES * DH4;
    scatter_convert_kernel<<<(sc_threads + 255) / 256, 256>>>(rows, embeds, E2);

    const int spmm_blocks = (N_NODES + 7) / 8;       // 8 warps (nodes) per block
    spmm_kernel<0><<<spmm_blocks, 256>>>();
    spmm_kernel<1><<<spmm_blocks, 256>>>();

    final_kernel<<<(3 * B + 7) / 8, 256>>>(embeds, users, pos, neg, out, B);
}

// round 10
// speedup vs baseline: 1.0394x; 1.0394x over previous
#include <cuda_runtime.h>
#include <cuda_fp16.h>
#include <cstdint>

#define N_USERS 100000
#define N_ITEMS 50000
#define N_NODES (N_USERS + N_ITEMS)   // 150000
#define D 64
#define DH4 (D / 8)                   // 8 uint4 (8 halves each) per row
#define MAX_E 4000000

#define SCAN_BLK  1024
#define SCAN_TILE (SCAN_BLK * 4)                           // 4096
#define SCAN_NB   ((N_ITEMS + SCAN_TILE - 1) / SCAN_TILE)  // 13

// ---------------- static device scratch -------------------------------------
// INVARIANT: g_count == 0 at entry of every kernel_launch call.
// (zero at load; scanA_kernel restores zeros after consuming the counts)
__device__ int   g_count[(N_ITEMS + 3) & ~3];
__device__ int   g_wcur [N_ITEMS];
__device__ int   g_ptr  [N_NODES + 1];
__device__ int   g_bsum [SCAN_NB];
__device__ int   g_edge [MAX_E];                       // 4B neighbor index only
__device__ uint4 g_t0   [(size_t)N_NODES * DH4];       // inv*emb (fp16)
__device__ uint4 g_t1   [(size_t)N_NODES * DH4];       // inv*c1  (fp16)
__device__ uint4 g_t2   [(size_t)N_NODES * DH4];       // inv*c2  (fp16)

// ---------------- step 1: user ptrs + edge pack + item histogram (fused) ----
__global__ void build1_kernel(const int* __restrict__ rows,
                              const int* __restrict__ cols, int E2) {
    int idx = blockIdx.x * blockDim.x + threadIdx.x;
    if (idx < E2) {
        int c = cols[idx];                 // item node id (item + N_USERS)
        g_edge[idx] = c;
        atomicAdd(&g_count[c - N_USERS], 1);
    }
    if (idx < N_USERS) {
        int lo = 0, hi = E2;
        while (lo < hi) {
            int m = (lo + hi) >> 1;
            if (rows[m] < idx) lo = m + 1; else hi = m;
        }
        g_ptr[idx] = lo;
    }
}

// ---------------- step 2a: per-block local exclusive scan (+count reset) ----
__global__ void scanA_kernel() {
    __shared__ int wsum[32];
    const int tid  = threadIdx.x;
    const int lane = tid & 31;
    const int wid  = tid >> 5;
    int base = blockIdx.x * SCAN_TILE + tid * 4;

    int4 v = make_int4(0, 0, 0, 0);
    if (base < N_ITEMS) {
        v = *(const int4*)&g_count[base];
        *(int4*)&g_count[base] = make_int4(0, 0, 0, 0);   // restore invariant
    }
    if (base >= N_ITEMS)     v.x = 0;
    if (base + 1 >= N_ITEMS) v.y = 0;
    if (base + 2 >= N_ITEMS) v.z = 0;
    if (base + 3 >= N_ITEMS) v.w = 0;

    int t = v.x + v.y + v.z + v.w;
    int x = t;
    #pragma unroll
    for (int o = 1; o < 32; o <<= 1) {
        int y = __shfl_up_sync(0xffffffffu, x, o);
        if (lane >= o) x += y;
    }
    if (lane == 31) wsum[wid] = x;
    __syncthreads();
    if (wid == 0) {
        int w = wsum[lane];
        int xs = w;
        #pragma unroll
        for (int o = 1; o < 32; o <<= 1) {
            int y = __shfl_up_sync(0xffffffffu, xs, o);
            if (lane >= o) xs += y;
        }
        wsum[lane] = xs - w;
    }
    __syncthreads();
    int excl = (x - t) + wsum[wid];

    int e0 = excl;
    int e1 = e0 + v.x;
    int e2 = e1 + v.y;
    int e3 = e2 + v.z;
    if (base < N_ITEMS) {
        int lim = N_ITEMS - base;
        int* p = &g_ptr[N_USERS + base];
        if (lim > 0) p[0] = e0;
        if (lim > 1) p[1] = e1;
        if (lim > 2) p[2] = e2;
        if (lim > 3) p[3] = e3;
    }
    if (tid == SCAN_BLK - 1) g_bsum[blockIdx.x] = e3 + v.w;
}

// ---------------- step 2b: apply tile offsets --------------------------------
__global__ void scanC_kernel(int E2) {
    int gid = blockIdx.x * blockDim.x + threadIdx.x;
    int i4 = gid * 4;
    if (gid == 0) {
        int tot = E2;
        #pragma unroll
        for (int j = 0; j < SCAN_NB; j++) tot += g_bsum[j];
        g_ptr[N_NODES] = tot;              // == E
    }
    if (i4 >= N_ITEMS) return;
    int tile = i4 / SCAN_TILE;
    int off = E2;
    for (int j = 0; j < tile; j++) off += g_bsum[j];
    int lim = N_ITEMS - i4;
    int* p = &g_ptr[N_USERS + i4];
    #pragma unroll
    for (int k = 0; k < 4; k++) {
        if (k < lim) {
            int val = p[k] + off;
            p[k] = val;
            g_wcur[i4 + k] = val;
        }
    }
}

// ---------------- step 3: scatter item-half edges + scaled fp16 convert -----
// scatter: 4 edges per thread (vectorized reads); payload from rows + hot g_edge.
// convert: t0[n] = rsqrt(deg(n)) * embeds[n].
__global__ void scatter_convert_kernel(const int* __restrict__ rows,
                                       const float* __restrict__ embeds,
                                       int E2) {
    int idx = blockIdx.x * blockDim.x + threadIdx.x;
    int E2q = (E2 + 3) >> 2;               // scatter thread count

    if (idx < E2q) {
        int base = idx * 4;
        if (base + 3 < E2) {
            int4 cv = *(const int4*)&g_edge[base];   // item node ids
            int4 rv = *(const int4*)&rows[base];     // user ids
            int p0 = atomicAdd(&g_wcur[cv.x - N_USERS], 1);
            int p1 = atomicAdd(&g_wcur[cv.y - N_USERS], 1);
            int p2 = atomicAdd(&g_wcur[cv.z - N_USERS], 1);
            int p3 = atomicAdd(&g_wcur[cv.w - N_USERS], 1);
            g_edge[p0] = rv.x;
            g_edge[p1] = rv.y;
            g_edge[p2] = rv.z;
            g_edge[p3] = rv.w;
        } else {
            for (int k = base; k < E2; k++) {
                int c = g_edge[k];
                int p = atomicAdd(&g_wcur[c - N_USERS], 1);
                g_edge[p] = rows[k];
            }
        }
    }

    int cidx = idx - E2q;
    if (cidx >= 0 && cidx < N_NODES * DH4) {
        int node = cidx >> 3;
        int deg  = g_ptr[node + 1] - g_ptr[node];
        float inv = (deg > 0) ? rsqrtf((float)deg) : 0.f;
        const float4* e4 = (const float4*)embeds;
        float4 f0 = e4[2 * cidx];
        float4 f1 = e4[2 * cidx + 1];
        __half2 h0 = __floats2half2_rn(inv * f0.x, inv * f0.y);
        __half2 h1 = __floats2half2_rn(inv * f0.z, inv * f0.w);
        __half2 h2 = __floats2half2_rn(inv * f1.x, inv * f1.y);
        __half2 h3 = __floats2half2_rn(inv * f1.z, inv * f1.w);
        uint4 u;
        u.x = *(const unsigned*)&h0;
        u.y = *(const unsigned*)&h1;
        u.z = *(const unsigned*)&h2;
        u.w = *(const unsigned*)&h3;
        g_t0[cidx] = u;
    }
}

// ---------------- SpMM helpers -----------------------------------------------
__device__ __forceinline__ void add8(float* s, uint4 x) {
    float2 f0 = __half22float2(*(const __half2*)&x.x);
    float2 f1 = __half22float2(*(const __half2*)&x.y);
    float2 f2 = __half22float2(*(const __half2*)&x.z);
    float2 f3 = __half22float2(*(const __half2*)&x.w);
    s[0] += f0.x; s[1] += f0.y;
    s[2] += f1.x; s[3] += f1.y;
    s[4] += f2.x; s[5] += f2.y;
    s[6] += f3.x; s[7] += f3.y;
}

__device__ __forceinline__ uint4 pack8s(const float* s, float w) {
    __half2 h0 = __floats2half2_rn(w * s[0], w * s[1]);
    __half2 h1 = __floats2half2_rn(w * s[2], w * s[3]);
    __half2 h2 = __floats2half2_rn(w * s[4], w * s[5]);
    __half2 h3 = __floats2half2_rn(w * s[6], w * s[7]);
    uint4 u;
    u.x = *(const unsigned*)&h0;
    u.y = *(const unsigned*)&h1;
    u.z = *(const unsigned*)&h2;
    u.w = *(const unsigned*)&h3;
    return u;
}

// ---------------- SpMM: t_{k+1}[n] = (sum_{c in N(n)} t_k[c]) / deg(n) ------
// 8 lanes per destination node; lane owns one uint4 (8 halves) of the row.
template <int LAYER>   // 0: t0 -> t1,  1: t1 -> t2
__global__ void spmm_kernel() {
    int node = (blockIdx.x * blockDim.x + threadIdx.x) >> 3;
    int ln   = threadIdx.x & 7;
    if (node >= N_NODES) return;

    const uint4* __restrict__ src = (LAYER == 0) ? g_t0 : g_t1;
    uint4* __restrict__ dst       = (LAYER == 0) ? g_t1 : g_t2;

    int beg = g_ptr[node];
    int end = g_ptr[node + 1];

    float s[8] = {0.f, 0.f, 0.f, 0.f, 0.f, 0.f, 0.f, 0.f};
    int e = beg;
    for (; e + 3 < end; e += 4) {
        int a = g_edge[e];
        int b = g_edge[e + 1];
        int c = g_edge[e + 2];
        int d = g_edge[e + 3];
        uint4 xa = src[(size_t)a * DH4 + ln];
        uint4 xb = src[(size_t)b * DH4 + ln];
        uint4 xc = src[(size_t)c * DH4 + ln];
        uint4 xd = src[(size_t)d * DH4 + ln];
        add8(s, xa); add8(s, xb); add8(s, xc); add8(s, xd);
    }
    for (; e < end; e++) {
        uint4 xa = src[(size_t)g_edge[e] * DH4 + ln];
        add8(s, xa);
    }

    int deg = end - beg;
    float w = (deg > 0) ? (1.f / (float)deg) : 0.f;
    dst[(size_t)node * DH4 + ln] = pack8s(s, w);
}

// ---------------- fused layer-3 SpMM + final gather -------------------------
// out = 0.25 * ( emb[n] + (t1[n]+t2[n])*sqrt(deg) + rsqrt(deg)*sum_c t2[c] )
__global__ void final_kernel(const float* __restrict__ embeds,
                             const int* __restrict__ users,
                             const int* __restrict__ pos,
                             const int* __restrict__ neg,
                             float4* __restrict__ out, int B) {
    int row = (blockIdx.x * blockDim.x + threadIdx.x) >> 3;
    int ln  = threadIdx.x & 7;
    if (row >= 3 * B) return;
    int grp = row / B;
    int r   = row - grp * B;
    int n;
    if (grp == 0)      n = users[r];
    else if (grp == 1) n = pos[r] + N_USERS;
    else               n = neg[r] + N_USERS;

    int beg = g_ptr[n];
    int end = g_ptr[n + 1];
    float s[8] = {0.f, 0.f, 0.f, 0.f, 0.f, 0.f, 0.f, 0.f};
    int e = beg;
    for (; e + 3 < end; e += 4) {
        int a = g_edge[e];
        int b = g_edge[e + 1];
        int c = g_edge[e + 2];
        int d = g_edge[e + 3];
        uint4 xa = g_t2[(size_t)a * DH4 + ln];
        uint4 xb = g_t2[(size_t)b * DH4 + ln];
        uint4 xc = g_t2[(size_t)c * DH4 + ln];
        uint4 xd = g_t2[(size_t)d * DH4 + ln];
        add8(s, xa); add8(s, xb); add8(s, xc); add8(s, xd);
    }
    for (; e < end; e++) {
        uint4 xa = g_t2[(size_t)g_edge[e] * DH4 + ln];
        add8(s, xa);
    }

    int deg = end - beg;
    float sq  = (deg > 0) ? sqrtf((float)deg)  : 0.f;
    float inv = (deg > 0) ? rsqrtf((float)deg) : 0.f;

    size_t ni = (size_t)n * DH4 + ln;
    const float4* e4 = (const float4*)embeds;
    float4 f0 = e4[2 * ni];
    float4 f1 = e4[2 * ni + 1];
    uint4 u1 = g_t1[ni];
    uint4 u2 = g_t2[ni];

    float tf[8];
    {
        float2 a0 = __half22float2(*(const __half2*)&u1.x);
        float2 a1 = __half22float2(*(const __half2*)&u1.y);
        float2 a2 = __half22float2(*(const __half2*)&u1.z);
        float2 a3 = __half22float2(*(const __half2*)&u1.w);
        float2 b0 = __half22float2(*(const __half2*)&u2.x);
        float2 b1 = __half22float2(*(const __half2*)&u2.y);
        float2 b2 = __half22float2(*(const __half2*)&u2.z);
        float2 b3 = __half22float2(*(const __half2*)&u2.w);
        tf[0] = a0.x + b0.x; tf[1] = a0.y + b0.y;
        tf[2] = a1.x + b1.x; tf[3] = a1.y + b1.y;
        tf[4] = a2.x + b2.x; tf[5] = a2.y + b2.y;
        tf[6] = a3.x + b3.x; tf[7] = a3.y + b3.y;
    }

    float4 o0, o1;
    o0.x = 0.25f * (f0.x + tf[0] * sq + s[0] * inv);
    o0.y = 0.25f * (f0.y + tf[1] * sq + s[1] * inv);
    o0.z = 0.25f * (f0.z + tf[2] * sq + s[2] * inv);
    o0.w = 0.25f * (f0.w + tf[3] * sq + s[3] * inv);
    o1.x = 0.25f * (f1.x + tf[4] * sq + s[4] * inv);
    o1.y = 0.25f * (f1.y + tf[5] * sq + s[5] * inv);
    o1.z = 0.25f * (f1.z + tf[6] * sq + s[6] * inv);
    o1.w = 0.25f * (f1.w + tf[7] * sq + s[7] * inv);
    size_t oi = (size_t)row * DH4 + ln;
    out[2 * oi]     = o0;
    out[2 * oi + 1] = o1;
}

// ---------------- launch -----------------------------------------------------
extern "C" void kernel_launch(void* const* d_in, const int* in_sizes, int n_in,
                              void* d_out, int out_size) {
    const float* embeds = (const float*)d_in[0];
    const int*   rows   = (const int*)d_in[2];
    const int*   cols   = (const int*)d_in[3];
    const int*   users  = (const int*)d_in[4];
    const int*   pos    = (const int*)d_in[5];
    const int*   neg    = (const int*)d_in[6];
    const int E  = in_sizes[1];
    const int E2 = E >> 1;
    const int B  = in_sizes[4];
    float4* out = (float4*)d_out;

    build1_kernel<<<(E2 + 255) / 256, 256>>>(rows, cols, E2);
    scanA_kernel<<<SCAN_NB, SCAN_BLK>>>();
    scanC_kernel<<<(N_ITEMS / 4 + 256) / 256, 256>>>(E2);

    int E2q = (E2 + 3) >> 2;
    int sc_threads = E2q + N_NODES * DH4;
    scatter_convert_kernel<<<(sc_threads + 255) / 256, 256>>>(rows, embeds, E2);

    const int spmm_blocks = (N_NODES * 8 + 255) / 256;
    spmm_kernel<0><<<spmm_blocks, 256>>>();
    spmm_kernel<1><<<spmm_blocks, 256>>>();

    final_kernel<<<(3 * B * 8 + 255) / 256, 256>>>(embeds, users, pos, neg, out, B);
}

// round 11
// speedup vs baseline: 1.0723x; 1.0316x over previous
#include <cuda_runtime.h>
#include <cuda_fp16.h>
#include <cstdint>

#define N_USERS 100000
#define N_ITEMS 50000
#define N_NODES (N_USERS + N_ITEMS)   // 150000
#define D 64
#define DH4 (D / 8)                   // 8 uint4 (8 halves each) per row
#define MAX_E 4000000

#define SCAN_BLK  1024
#define SCAN_TILE (SCAN_BLK * 4)                           // 4096
#define SCAN_NB   ((N_ITEMS + SCAN_TILE - 1) / SCAN_TILE)  // 13

// ---------------- static device scratch -------------------------------------
// INVARIANT: g_count == 0 at entry of every kernel_launch call.
// (zero at load; scanA_kernel restores zeros after consuming the counts)
__device__ int   g_count[(N_ITEMS + 3) & ~3];
__device__ int   g_wcur [N_ITEMS];
__device__ int   g_ptr  [N_NODES + 1];
__device__ int   g_bsum [SCAN_NB];
__device__ int   g_edge [MAX_E];                       // 4B neighbor index only
__device__ uint4 g_t0   [(size_t)N_NODES * DH4];       // inv*emb (fp16)
__device__ uint4 g_t1   [(size_t)N_NODES * DH4];       // inv*c1  (fp16)
__device__ uint4 g_t2   [(size_t)N_NODES * DH4];       // inv*c2  (fp16)

// ---------------- step 1: user ptrs + edge pack + item histogram (fused) ----
__global__ void build1_kernel(const int* __restrict__ rows,
                              const int* __restrict__ cols, int E2) {
    int idx = blockIdx.x * blockDim.x + threadIdx.x;
    if (idx < E2) {
        int c = cols[idx];                 // item node id (item + N_USERS)
        g_edge[idx] = c;
        atomicAdd(&g_count[c - N_USERS], 1);
    }
    if (idx < N_USERS) {
        int lo = 0, hi = E2;
        while (lo < hi) {
            int m = (lo + hi) >> 1;
            if (rows[m] < idx) lo = m + 1; else hi = m;
        }
        g_ptr[idx] = lo;
    }
}

// ---------------- step 2a: per-block local exclusive scan (+count reset) ----
__global__ void scanA_kernel() {
    __shared__ int wsum[32];
    const int tid  = threadIdx.x;
    const int lane = tid & 31;
    const int wid  = tid >> 5;
    int base = blockIdx.x * SCAN_TILE + tid * 4;

    int4 v = make_int4(0, 0, 0, 0);
    if (base < N_ITEMS) {
        v = *(const int4*)&g_count[base];
        *(int4*)&g_count[base] = make_int4(0, 0, 0, 0);   // restore invariant
    }
    if (base >= N_ITEMS)     v.x = 0;
    if (base + 1 >= N_ITEMS) v.y = 0;
    if (base + 2 >= N_ITEMS) v.z = 0;
    if (base + 3 >= N_ITEMS) v.w = 0;

    int t = v.x + v.y + v.z + v.w;
    int x = t;
    #pragma unroll
    for (int o = 1; o < 32; o <<= 1) {
        int y = __shfl_up_sync(0xffffffffu, x, o);
        if (lane >= o) x += y;
    }
    if (lane == 31) wsum[wid] = x;
    __syncthreads();
    if (wid == 0) {
        int w = wsum[lane];
        int xs = w;
        #pragma unroll
        for (int o = 1; o < 32; o <<= 1) {
            int y = __shfl_up_sync(0xffffffffu, xs, o);
            if (lane >= o) xs += y;
        }
        wsum[lane] = xs - w;
    }
    __syncthreads();
    int excl = (x - t) + wsum[wid];

    int e0 = excl;
    int e1 = e0 + v.x;
    int e2 = e1 + v.y;
    int e3 = e2 + v.z;
    if (base < N_ITEMS) {
        int lim = N_ITEMS - base;
        int* p = &g_ptr[N_USERS + base];
        if (lim > 0) p[0] = e0;
        if (lim > 1) p[1] = e1;
        if (lim > 2) p[2] = e2;
        if (lim > 3) p[3] = e3;
    }
    if (tid == SCAN_BLK - 1) g_bsum[blockIdx.x] = e3 + v.w;
}

// ---------------- step 2b: apply tile offsets --------------------------------
__global__ void scanC_kernel(int E2) {
    int gid = blockIdx.x * blockDim.x + threadIdx.x;
    int i4 = gid * 4;
    if (gid == 0) {
        int tot = E2;
        #pragma unroll
        for (int j = 0; j < SCAN_NB; j++) tot += g_bsum[j];
        g_ptr[N_NODES] = tot;              // == E
    }
    if (i4 >= N_ITEMS) return;
    int tile = i4 / SCAN_TILE;
    int off = E2;
    for (int j = 0; j < tile; j++) off += g_bsum[j];
    int lim = N_ITEMS - i4;
    int* p = &g_ptr[N_USERS + i4];
    #pragma unroll
    for (int k = 0; k < 4; k++) {
        if (k < lim) {
            int val = p[k] + off;
            p[k] = val;
            g_wcur[i4 + k] = val;
        }
    }
}

// ---------------- step 3: scatter item-half edges + scaled fp16 convert -----
// scatter: 4 edges per thread (vectorized reads); payload from rows + hot g_edge.
// convert: t0[n] = rsqrt(deg(n)) * embeds[n].
__global__ void scatter_convert_kernel(const int* __restrict__ rows,
                                       const float* __restrict__ embeds,
                                       int E2) {
    int idx = blockIdx.x * blockDim.x + threadIdx.x;
    int E2q = (E2 + 3) >> 2;               // scatter thread count

    if (idx < E2q) {
        int base = idx * 4;
        if (base + 3 < E2) {
            int4 cv = *(const int4*)&g_edge[base];   // item node ids
            int4 rv = *(const int4*)&rows[base];     // user ids
            int p0 = atomicAdd(&g_wcur[cv.x - N_USERS], 1);
            int p1 = atomicAdd(&g_wcur[cv.y - N_USERS], 1);
            int p2 = atomicAdd(&g_wcur[cv.z - N_USERS], 1);
            int p3 = atomicAdd(&g_wcur[cv.w - N_USERS], 1);
            g_edge[p0] = rv.x;
            g_edge[p1] = rv.y;
            g_edge[p2] = rv.z;
            g_edge[p3] = rv.w;
        } else {
            for (int k = base; k < E2; k++) {
                int c = g_edge[k];
                int p = atomicAdd(&g_wcur[c - N_USERS], 1);
                g_edge[p] = rows[k];
            }
        }
    }

    int cidx = idx - E2q;
    if (cidx >= 0 && cidx < N_NODES * DH4) {
        int node = cidx >> 3;
        int deg  = g_ptr[node + 1] - g_ptr[node];
        float inv = (deg > 0) ? rsqrtf((float)deg) : 0.f;
        const float4* e4 = (const float4*)embeds;
        float4 f0 = e4[2 * cidx];
        float4 f1 = e4[2 * cidx + 1];
        __half2 h0 = __floats2half2_rn(inv * f0.x, inv * f0.y);
        __half2 h1 = __floats2half2_rn(inv * f0.z, inv * f0.w);
        __half2 h2 = __floats2half2_rn(inv * f1.x, inv * f1.y);
        __half2 h3 = __floats2half2_rn(inv * f1.z, inv * f1.w);
        uint4 u;
        u.x = *(const unsigned*)&h0;
        u.y = *(const unsigned*)&h1;
        u.z = *(const unsigned*)&h2;
        u.w = *(const unsigned*)&h3;
        g_t0[cidx] = u;
    }
}

// ---------------- SpMM helpers -----------------------------------------------
__device__ __forceinline__ void add8(float* s, uint4 x) {
    float2 f0 = __half22float2(*(const __half2*)&x.x);
    float2 f1 = __half22float2(*(const __half2*)&x.y);
    float2 f2 = __half22float2(*(const __half2*)&x.z);
    float2 f3 = __half22float2(*(const __half2*)&x.w);
    s[0] += f0.x; s[1] += f0.y;
    s[2] += f1.x; s[3] += f1.y;
    s[4] += f2.x; s[5] += f2.y;
    s[6] += f3.x; s[7] += f3.y;
}

__device__ __forceinline__ uint4 pack8s(const float* s, float w) {
    __half2 h0 = __floats2half2_rn(w * s[0], w * s[1]);
    __half2 h1 = __floats2half2_rn(w * s[2], w * s[3]);
    __half2 h2 = __floats2half2_rn(w * s[4], w * s[5]);
    __half2 h3 = __floats2half2_rn(w * s[6], w * s[7]);
    uint4 u;
    u.x = *(const unsigned*)&h0;
    u.y = *(const unsigned*)&h1;
    u.z = *(const unsigned*)&h2;
    u.w = *(const unsigned*)&h3;
    return u;
}

// ---------------- SpMM: t_{k+1}[n] = (sum_{c in N(n)} t_k[c]) / deg(n) ------
// 8 lanes per destination node; lane owns one uint4 (8 halves) of the row.
template <int LAYER>   // 0: t0 -> t1,  1: t1 -> t2
__global__ void spmm_kernel() {
    int node = (blockIdx.x * blockDim.x + threadIdx.x) >> 3;
    int ln   = threadIdx.x & 7;
    if (node >= N_NODES) return;

    const uint4* __restrict__ src = (LAYER == 0) ? g_t0 : g_t1;
    uint4* __restrict__ dst       = (LAYER == 0) ? g_t1 : g_t2;

    int beg = g_ptr[node];
    int end = g_ptr[node + 1];

    float s[8] = {0.f, 0.f, 0.f, 0.f, 0.f, 0.f, 0.f, 0.f};
    int e = beg;
    for (; e + 3 < end; e += 4) {
        int a = g_edge[e];
        int b = g_edge[e + 1];
        int c = g_edge[e + 2];
        int d = g_edge[e + 3];
        uint4 xa = src[(size_t)a * DH4 + ln];
        uint4 xb = src[(size_t)b * DH4 + ln];
        uint4 xc = src[(size_t)c * DH4 + ln];
        uint4 xd = src[(size_t)d * DH4 + ln];
        add8(s, xa); add8(s, xb); add8(s, xc); add8(s, xd);
    }
    for (; e < end; e++) {
        uint4 xa = src[(size_t)g_edge[e] * DH4 + ln];
        add8(s, xa);
    }

    int deg = end - beg;
    float w = (deg > 0) ? (1.f / (float)deg) : 0.f;
    dst[(size_t)node * DH4 + ln] = pack8s(s, w);
}

// ---------------- fused layer-3 SpMM + final gather -------------------------
// out = 0.25 * ( emb[n] + (t1[n]+t2[n])*sqrt(deg) + rsqrt(deg)*sum_c t2[c] )
__global__ void final_kernel(const float* __restrict__ embeds,
                             const int* __restrict__ users,
                             const int* __restrict__ pos,
                             const int* __restrict__ neg,
                             float4* __restrict__ out, int B) {
    int row = (blockIdx.x * blockDim.x + threadIdx.x) >> 3;
    int ln  = threadIdx.x & 7;
    if (row >= 3 * B) return;
    int grp = row / B;
    int r   = row - grp * B;
    int n;
    if (grp == 0)      n = users[r];
    else if (grp == 1) n = pos[r] + N_USERS;
    else               n = neg[r] + N_USERS;

    int beg = g_ptr[n];
    int end = g_ptr[n + 1];
    float s[8] = {0.f, 0.f, 0.f, 0.f, 0.f, 0.f, 0.f, 0.f};
    int e = beg;
    for (; e + 3 < end; e += 4) {
        int a = g_edge[e];
        int b = g_edge[e + 1];
        int c = g_edge[e + 2];
        int d = g_edge[e + 3];
        uint4 xa = g_t2[(size_t)a * DH4 + ln];
        uint4 xb = g_t2[(size_t)b * DH4 + ln];
        uint4 xc = g_t2[(size_t)c * DH4 + ln];
        uint4 xd = g_t2[(size_t)d * DH4 + ln];
        add8(s, xa); add8(s, xb); add8(s, xc); add8(s, xd);
    }
    for (; e < end; e++) {
        uint4 xa = g_t2[(size_t)g_edge[e] * DH4 + ln];
        add8(s, xa);
    }

    int deg = end - beg;
    float sq  = (deg > 0) ? sqrtf((float)deg)  : 0.f;
    float inv = (deg > 0) ? rsqrtf((float)deg) : 0.f;

    size_t ni = (size_t)n * DH4 + ln;
    const float4* e4 = (const float4*)embeds;
    float4 f0 = e4[2 * ni];
    float4 f1 = e4[2 * ni + 1];
    uint4 u1 = g_t1[ni];
    uint4 u2 = g_t2[ni];

    float tf[8];
    {
        float2 a0 = __half22float2(*(const __half2*)&u1.x);
        float2 a1 = __half22float2(*(const __half2*)&u1.y);
        float2 a2 = __half22float2(*(const __half2*)&u1.z);
        float2 a3 = __half22float2(*(const __half2*)&u1.w);
        float2 b0 = __half22float2(*(const __half2*)&u2.x);
        float2 b1 = __half22float2(*(const __half2*)&u2.y);
        float2 b2 = __half22float2(*(const __half2*)&u2.z);
        float2 b3 = __half22float2(*(const __half2*)&u2.w);
        tf[0] = a0.x + b0.x; tf[1] = a0.y + b0.y;
        tf[2] = a1.x + b1.x; tf[3] = a1.y + b1.y;
        tf[4] = a2.x + b2.x; tf[5] = a2.y + b2.y;
        tf[6] = a3.x + b3.x; tf[7] = a3.y + b3.y;
    }

    float4 o0, o1;
    o0.x = 0.25f * (f0.x + tf[0] * sq + s[0] * inv);
    o0.y = 0.25f * (f0.y + tf[1] * sq + s[1] * inv);
    o0.z = 0.25f * (f0.z + tf[2] * sq + s[2] * inv);
    o0.w = 0.25f * (f0.w + tf[3] * sq + s[3] * inv);
    o1.x = 0.25f * (f1.x + tf[4] * sq + s[4] * inv);
    o1.y = 0.25f * (f1.y + tf[5] * sq + s[5] * inv);
    o1.z = 0.25f * (f1.z + tf[6] * sq + s[6] * inv);
    o1.w = 0.25f * (f1.w + tf[7] * sq + s[7] * inv);
    size_t oi = (size_t)row * DH4 + ln;
    out[2 * oi]     = o0;
    out[2 * oi + 1] = o1;
}

// ---------------- launch -----------------------------------------------------
extern "C" void kernel_launch(void* const* d_in, const int* in_sizes, int n_in,
                              void* d_out, int out_size) {
    const float* embeds = (const float*)d_in[0];
    const int*   rows   = (const int*)d_in[2];
    const int*   cols   = (const int*)d_in[3];
    const int*   users  = (const int*)d_in[4];
    const int*   pos    = (const int*)d_in[5];
    const int*   neg    = (const int*)d_in[6];
    const int E  = in_sizes[1];
    const int E2 = E >> 1;
    const int B  = in_sizes[4];
    float4* out = (float4*)d_out;

    build1_kernel<<<(E2 + 255) / 256, 256>>>(rows, cols, E2);
    scanA_kernel<<<SCAN_NB, SCAN_BLK>>>();
    scanC_kernel<<<(N_ITEMS / 4 + 256) / 256, 256>>>(E2);

    int E2q = (E2 + 3) >> 2;
    int sc_threads = E2q + N_NODES * DH4;
    scatter_convert_kernel<<<(sc_threads + 255) / 256, 256>>>(rows, embeds, E2);

    const int spmm_blocks = (N_NODES * 8 + 255) / 256;
    spmm_kernel<0><<<spmm_blocks, 256>>>();
    spmm_kernel<1><<<spmm_blocks, 256>>>();

    final_kernel<<<(3 * B * 8 + 255) / 256, 256>>>(embeds, users, pos, neg, out, B);
}

// round 12
// speedup vs baseline: 1.0754x; 1.0029x over previous
#include <cuda_runtime.h>
#include <cuda_fp16.h>
#include <cstdint>

#define N_USERS 100000
#define N_ITEMS 50000
#define N_NODES (N_USERS + N_ITEMS)   // 150000
#define D 64
#define DH4 (D / 8)                   // 8 uint4 (8 halves each) per row
#define MAX_E 4000000

#define SCAN_BLK  1024
#define SCAN_TILE (SCAN_BLK * 4)                           // 4096
#define SCAN_NB   ((N_ITEMS + SCAN_TILE - 1) / SCAN_TILE)  // 13

// ---------------- static device scratch -------------------------------------
// INVARIANT: g_count == 0 at entry of every kernel_launch call.
// (zero at load; scanA_kernel restores zeros after consuming the counts)
__device__ int   g_count[(N_ITEMS + 3) & ~3];
__device__ int   g_wcur [N_ITEMS];
__device__ int   g_ptr  [N_NODES + 1];
__device__ int   g_bsum [SCAN_NB];
__device__ int   g_edge [MAX_E];                       // 4B neighbor index only
__device__ uint4 g_t0   [(size_t)N_NODES * DH4];       // inv*emb (fp16)
__device__ uint4 g_t1   [(size_t)N_NODES * DH4];       // inv*c1  (fp16)
__device__ uint4 g_t2   [(size_t)N_NODES * DH4];       // inv*c2  (fp16)

// ---------------- step 1: user ptrs + edge pack + item histogram (fused) ----
__global__ void build1_kernel(const int* __restrict__ rows,
                              const int* __restrict__ cols, int E2) {
    int idx = blockIdx.x * blockDim.x + threadIdx.x;
    if (idx < E2) {
        int c = cols[idx];                 // item node id (item + N_USERS)
        g_edge[idx] = c;
        atomicAdd(&g_count[c - N_USERS], 1);
    }
    if (idx < N_USERS) {
        int lo = 0, hi = E2;
        while (lo < hi) {
            int m = (lo + hi) >> 1;
            if (rows[m] < idx) lo = m + 1; else hi = m;
        }
        g_ptr[idx] = lo;
    }
}

// ---------------- step 2a: per-block local exclusive scan (+count reset) ----
__global__ void scanA_kernel() {
    __shared__ int wsum[32];
    const int tid  = threadIdx.x;
    const int lane = tid & 31;
    const int wid  = tid >> 5;
    int base = blockIdx.x * SCAN_TILE + tid * 4;

    int4 v = make_int4(0, 0, 0, 0);
    if (base < N_ITEMS) {
        v = *(const int4*)&g_count[base];
        *(int4*)&g_count[base] = make_int4(0, 0, 0, 0);   // restore invariant
    }
    if (base >= N_ITEMS)     v.x = 0;
    if (base + 1 >= N_ITEMS) v.y = 0;
    if (base + 2 >= N_ITEMS) v.z = 0;
    if (base + 3 >= N_ITEMS) v.w = 0;

    int t = v.x + v.y + v.z + v.w;
    int x = t;
    #pragma unroll
    for (int o = 1; o < 32; o <<= 1) {
        int y = __shfl_up_sync(0xffffffffu, x, o);
        if (lane >= o) x += y;
    }
    if (lane == 31) wsum[wid] = x;
    __syncthreads();
    if (wid == 0) {
        int w = wsum[lane];
        int xs = w;
        #pragma unroll
        for (int o = 1; o < 32; o <<= 1) {
            int y = __shfl_up_sync(0xffffffffu, xs, o);
            if (lane >= o) xs += y;
        }
        wsum[lane] = xs - w;
    }
    __syncthreads();
    int excl = (x - t) + wsum[wid];

    int e0 = excl;
    int e1 = e0 + v.x;
    int e2 = e1 + v.y;
    int e3 = e2 + v.z;
    if (base < N_ITEMS) {
        int lim = N_ITEMS - base;
        int* p = &g_ptr[N_USERS + base];
        if (lim > 0) p[0] = e0;
        if (lim > 1) p[1] = e1;
        if (lim > 2) p[2] = e2;
        if (lim > 3) p[3] = e3;
    }
    if (tid == SCAN_BLK - 1) g_bsum[blockIdx.x] = e3 + v.w;
}

// ---------------- step 2b: apply tile offsets --------------------------------
__global__ void scanC_kernel(int E2) {
    int gid = blockIdx.x * blockDim.x + threadIdx.x;
    int i4 = gid * 4;
    if (gid == 0) {
        int tot = E2;
        #pragma unroll
        for (int j = 0; j < SCAN_NB; j++) tot += g_bsum[j];
        g_ptr[N_NODES] = tot;              // == E
    }
    if (i4 >= N_ITEMS) return;
    int tile = i4 / SCAN_TILE;
    int off = E2;
    for (int j = 0; j < tile; j++) off += g_bsum[j];
    int lim = N_ITEMS - i4;
    int* p = &g_ptr[N_USERS + i4];
    #pragma unroll
    for (int k = 0; k < 4; k++) {
        if (k < lim) {
            int val = p[k] + off;
            p[k] = val;
            g_wcur[i4 + k] = val;
        }
    }
}

// ---------------- step 3: scatter item-half edges + scaled fp16 convert -----
// scatter: 4 edges per thread (vectorized reads); payload from rows + hot g_edge.
// convert: t0[n] = rsqrt(deg(n)) * embeds[n].
__global__ void scatter_convert_kernel(const int* __restrict__ rows,
                                       const float* __restrict__ embeds,
                                       int E2) {
    int idx = blockIdx.x * blockDim.x + threadIdx.x;
    int E2q = (E2 + 3) >> 2;               // scatter thread count

    if (idx < E2q) {
        int base = idx * 4;
        if (base + 3 < E2) {
            int4 cv = *(const int4*)&g_edge[base];   // item node ids
            int4 rv = *(const int4*)&rows[base];     // user ids
            int p0 = atomicAdd(&g_wcur[cv.x - N_USERS], 1);
            int p1 = atomicAdd(&g_wcur[cv.y - N_USERS], 1);
            int p2 = atomicAdd(&g_wcur[cv.z - N_USERS], 1);
            int p3 = atomicAdd(&g_wcur[cv.w - N_USERS], 1);
            g_edge[p0] = rv.x;
            g_edge[p1] = rv.y;
            g_edge[p2] = rv.z;
            g_edge[p3] = rv.w;
        } else {
            for (int k = base; k < E2; k++) {
                int c = g_edge[k];
                int p = atomicAdd(&g_wcur[c - N_USERS], 1);
                g_edge[p] = rows[k];
            }
        }
    }

    int cidx = idx - E2q;
    if (cidx >= 0 && cidx < N_NODES * DH4) {
        int node = cidx >> 3;
        int deg  = g_ptr[node + 1] - g_ptr[node];
        float inv = (deg > 0) ? rsqrtf((float)deg) : 0.f;
        const float4* e4 = (const float4*)embeds;
        float4 f0 = e4[2 * cidx];
        float4 f1 = e4[2 * cidx + 1];
        __half2 h0 = __floats2half2_rn(inv * f0.x, inv * f0.y);
        __half2 h1 = __floats2half2_rn(inv * f0.z, inv * f0.w);
        __half2 h2 = __floats2half2_rn(inv * f1.x, inv * f1.y);
        __half2 h3 = __floats2half2_rn(inv * f1.z, inv * f1.w);
        uint4 u;
        u.x = *(const unsigned*)&h0;
        u.y = *(const unsigned*)&h1;
        u.z = *(const unsigned*)&h2;
        u.w = *(const unsigned*)&h3;
        g_t0[cidx] = u;
    }
}

// ---------------- SpMM helpers -----------------------------------------------
__device__ __forceinline__ void add8(float* s, uint4 x) {
    float2 f0 = __half22float2(*(const __half2*)&x.x);
    float2 f1 = __half22float2(*(const __half2*)&x.y);
    float2 f2 = __half22float2(*(const __half2*)&x.z);
    float2 f3 = __half22float2(*(const __half2*)&x.w);
    s[0] += f0.x; s[1] += f0.y;
    s[2] += f1.x; s[3] += f1.y;
    s[4] += f2.x; s[5] += f2.y;
    s[6] += f3.x; s[7] += f3.y;
}

__device__ __forceinline__ uint4 pack8s(const float* s, float w) {
    __half2 h0 = __floats2half2_rn(w * s[0], w * s[1]);
    __half2 h1 = __floats2half2_rn(w * s[2], w * s[3]);
    __half2 h2 = __floats2half2_rn(w * s[4], w * s[5]);
    __half2 h3 = __floats2half2_rn(w * s[6], w * s[7]);
    uint4 u;
    u.x = *(const unsigned*)&h0;
    u.y = *(const unsigned*)&h1;
    u.z = *(const unsigned*)&h2;
    u.w = *(const unsigned*)&h3;
    return u;
}

// ---------------- SpMM: t_{k+1}[n] = (sum_{c in N(n)} t_k[c]) / deg(n) ------
// 8 lanes per destination node; lane owns one uint4 (8 halves) of the row.
template <int LAYER>   // 0: t0 -> t1,  1: t1 -> t2
__global__ void spmm_kernel() {
    int node = (blockIdx.x * blockDim.x + threadIdx.x) >> 3;
    int ln   = threadIdx.x & 7;
    if (node >= N_NODES) return;

    const uint4* __restrict__ src = (LAYER == 0) ? g_t0 : g_t1;
    uint4* __restrict__ dst       = (LAYER == 0) ? g_t1 : g_t2;

    int beg = g_ptr[node];
    int end = g_ptr[node + 1];

    float s[8] = {0.f, 0.f, 0.f, 0.f, 0.f, 0.f, 0.f, 0.f};
    int e = beg;
    for (; e + 3 < end; e += 4) {
        int a = g_edge[e];
        int b = g_edge[e + 1];
        int c = g_edge[e + 2];
        int d = g_edge[e + 3];
        uint4 xa = src[(size_t)a * DH4 + ln];
        uint4 xb = src[(size_t)b * DH4 + ln];
        uint4 xc = src[(size_t)c * DH4 + ln];
        uint4 xd = src[(size_t)d * DH4 + ln];
        add8(s, xa); add8(s, xb); add8(s, xc); add8(s, xd);
    }
    for (; e < end; e++) {
        uint4 xa = src[(size_t)g_edge[e] * DH4 + ln];
        add8(s, xa);
    }

    int deg = end - beg;
    float w = (deg > 0) ? (1.f / (float)deg) : 0.f;
    dst[(size_t)node * DH4 + ln] = pack8s(s, w);
}

// ---------------- fused layer-3 SpMM + final gather -------------------------
// out = 0.25 * ( emb[n] + (t1[n]+t2[n])*sqrt(deg) + rsqrt(deg)*sum_c t2[c] )
__global__ void final_kernel(const float* __restrict__ embeds,
                             const int* __restrict__ users,
                             const int* __restrict__ pos,
                             const int* __restrict__ neg,
                             float4* __restrict__ out, int B) {
    int row = (blockIdx.x * blockDim.x + threadIdx.x) >> 3;
    int ln  = threadIdx.x & 7;
    if (row >= 3 * B) return;
    int grp = row / B;
    int r   = row - grp * B;
    int n;
    if (grp == 0)      n = users[r];
    else if (grp == 1) n = pos[r] + N_USERS;
    else               n = neg[r] + N_USERS;

    int beg = g_ptr[n];
    int end = g_ptr[n + 1];
    float s[8] = {0.f, 0.f, 0.f, 0.f, 0.f, 0.f, 0.f, 0.f};
    int e = beg;
    for (; e + 3 < end; e += 4) {
        int a = g_edge[e];
        int b = g_edge[e + 1];
        int c = g_edge[e + 2];
        int d = g_edge[e + 3];
        uint4 xa = g_t2[(size_t)a * DH4 + ln];
        uint4 xb = g_t2[(size_t)b * DH4 + ln];
        uint4 xc = g_t2[(size_t)c * DH4 + ln];
        uint4 xd = g_t2[(size_t)d * DH4 + ln];
        add8(s, xa); add8(s, xb); add8(s, xc); add8(s, xd);
    }
    for (; e < end; e++) {
        uint4 xa = g_t2[(size_t)g_edge[e] * DH4 + ln];
        add8(s, xa);
    }

    int deg = end - beg;
    float sq  = (deg > 0) ? sqrtf((float)deg)  : 0.f;
    float inv = (deg > 0) ? rsqrtf((float)deg) : 0.f;

    size_t ni = (size_t)n * DH4 + ln;
    const float4* e4 = (const float4*)embeds;
    float4 f0 = e4[2 * ni];
    float4 f1 = e4[2 * ni + 1];
    uint4 u1 = g_t1[ni];
    uint4 u2 = g_t2[ni];

    float tf[8];
    {
        float2 a0 = __half22float2(*(const __half2*)&u1.x);
        float2 a1 = __half22float2(*(const __half2*)&u1.y);
        float2 a2 = __half22float2(*(const __half2*)&u1.z);
        float2 a3 = __half22float2(*(const __half2*)&u1.w);
        float2 b0 = __half22float2(*(const __half2*)&u2.x);
        float2 b1 = __half22float2(*(const __half2*)&u2.y);
        float2 b2 = __half22float2(*(const __half2*)&u2.z);
        float2 b3 = __half22float2(*(const __half2*)&u2.w);
        tf[0] = a0.x + b0.x; tf[1] = a0.y + b0.y;
        tf[2] = a1.x + b1.x; tf[3] = a1.y + b1.y;
        tf[4] = a2.x + b2.x; tf[5] = a2.y + b2.y;
        tf[6] = a3.x + b3.x; tf[7] = a3.y + b3.y;
    }

    float4 o0, o1;
    o0.x = 0.25f * (f0.x + tf[0] * sq + s[0] * inv);
    o0.y = 0.25f * (f0.y + tf[1] * sq + s[1] * inv);
    o0.z = 0.25f * (f0.z + tf[2] * sq + s[2] * inv);
    o0.w = 0.25f * (f0.w + tf[3] * sq + s[3] * inv);
    o1.x = 0.25f * (f1.x + tf[4] * sq + s[4] * inv);
    o1.y = 0.25f * (f1.y + tf[5] * sq + s[5] * inv);
    o1.z = 0.25f * (f1.z + tf[6] * sq + s[6] * inv);
    o1.w = 0.25f * (f1.w + tf[7] * sq + s[7] * inv);
    size_t oi = (size_t)row * DH4 + ln;
    out[2 * oi]     = o0;
    out[2 * oi + 1] = o1;
}

// ---------------- launch -----------------------------------------------------
extern "C" void kernel_launch(void* const* d_in, const int* in_sizes, int n_in,
                              void* d_out, int out_size) {
    const float* embeds = (const float*)d_in[0];
    const int*   rows   = (const int*)d_in[2];
    const int*   cols   = (const int*)d_in[3];
    const int*   users  = (const int*)d_in[4];
    const int*   pos    = (const int*)d_in[5];
    const int*   neg    = (const int*)d_in[6];
    const int E  = in_sizes[1];
    const int E2 = E >> 1;
    const int B  = in_sizes[4];
    float4* out = (float4*)d_out;

    build1_kernel<<<(E2 + 255) / 256, 256>>>(rows, cols, E2);
    scanA_kernel<<<SCAN_NB, SCAN_BLK>>>();
    scanC_kernel<<<(N_ITEMS / 4 + 256) / 256, 256>>>(E2);

    int E2q = (E2 + 3) >> 2;
    int sc_threads = E2q + N_NODES * DH4;
    scatter_convert_kernel<<<(sc_threads + 255) / 256, 256>>>(rows, embeds, E2);

    const int spmm_blocks = (N_NODES * 8 + 255) / 256;
    spmm_kernel<0><<<spmm_blocks, 256>>>();
    spmm_kernel<1><<<spmm_blocks, 256>>>();

    final_kernel<<<(3 * B * 8 + 255) / 256, 256>>>(embeds, users, pos, neg, out, B);
}

// round 13
// speedup vs baseline: 1.0756x; 1.0002x over previous
#include <cuda_runtime.h>
#include <cuda_fp16.h>
#include <cstdint>

#define N_USERS 100000
#define N_ITEMS 50000
#define N_NODES (N_USERS + N_ITEMS)   // 150000
#define D 64
#define DH4 (D / 8)                   // 8 uint4 (8 halves each) per row
#define MAX_E 4000000

#define SCAN_BLK  1024
#define SCAN_TILE (SCAN_BLK * 4)                           // 4096
#define SCAN_NB   ((N_ITEMS + SCAN_TILE - 1) / SCAN_TILE)  // 13

// ---------------- static device scratch -------------------------------------
// INVARIANT: g_count == 0 at entry of every kernel_launch call.
// (zero at load; scanA_kernel restores zeros after consuming the counts)
__device__ int   g_count[(N_ITEMS + 3) & ~3];
__device__ int   g_wcur [N_ITEMS];
__device__ int   g_ptr  [N_NODES + 1];
__device__ int   g_bsum [SCAN_NB];
__device__ int   g_edge [MAX_E];                       // 4B neighbor index only
__device__ uint4 g_t0   [(size_t)N_NODES * DH4];       // inv*emb (fp16)
__device__ uint4 g_t1   [(size_t)N_NODES * DH4];       // inv*c1  (fp16)
__device__ uint4 g_t2   [(size_t)N_NODES * DH4];       // inv*c2  (fp16)

// ---------------- step 1: user ptrs + edge pack + item histogram (fused) ----
__global__ void build1_kernel(const int* __restrict__ rows,
                              const int* __restrict__ cols, int E2) {
    int idx = blockIdx.x * blockDim.x + threadIdx.x;
    if (idx < E2) {
        int c = cols[idx];                 // item node id (item + N_USERS)
        g_edge[idx] = c;
        atomicAdd(&g_count[c - N_USERS], 1);
    }
    if (idx < N_USERS) {
        int lo = 0, hi = E2;
        while (lo < hi) {
            int m = (lo + hi) >> 1;
            if (rows[m] < idx) lo = m + 1; else hi = m;
        }
        g_ptr[idx] = lo;
    }
}

// ---------------- step 2a: per-block local exclusive scan (+count reset) ----
__global__ void scanA_kernel() {
    __shared__ int wsum[32];
    const int tid  = threadIdx.x;
    const int lane = tid & 31;
    const int wid  = tid >> 5;
    int base = blockIdx.x * SCAN_TILE + tid * 4;

    int4 v = make_int4(0, 0, 0, 0);
    if (base < N_ITEMS) {
        v = *(const int4*)&g_count[base];
        *(int4*)&g_count[base] = make_int4(0, 0, 0, 0);   // restore invariant
    }
    if (base >= N_ITEMS)     v.x = 0;
    if (base + 1 >= N_ITEMS) v.y = 0;
    if (base + 2 >= N_ITEMS) v.z = 0;
    if (base + 3 >= N_ITEMS) v.w = 0;

    int t = v.x + v.y + v.z + v.w;
    int x = t;
    #pragma unroll
    for (int o = 1; o < 32; o <<= 1) {
        int y = __shfl_up_sync(0xffffffffu, x, o);
        if (lane >= o) x += y;
    }
    if (lane == 31) wsum[wid] = x;
    __syncthreads();
    if (wid == 0) {
        int w = wsum[lane];
        int xs = w;
        #pragma unroll
        for (int o = 1; o < 32; o <<= 1) {
            int y = __shfl_up_sync(0xffffffffu, xs, o);
            if (lane >= o) xs += y;
        }
        wsum[lane] = xs - w;
    }
    __syncthreads();
    int excl = (x - t) + wsum[wid];

    int e0 = excl;
    int e1 = e0 + v.x;
    int e2 = e1 + v.y;
    int e3 = e2 + v.z;
    if (base < N_ITEMS) {
        int lim = N_ITEMS - base;
        int* p = &g_ptr[N_USERS + base];
        if (lim > 0) p[0] = e0;
        if (lim > 1) p[1] = e1;
        if (lim > 2) p[2] = e2;
        if (lim > 3) p[3] = e3;
    }
    if (tid == SCAN_BLK - 1) g_bsum[blockIdx.x] = e3 + v.w;
}

// ---------------- step 2b: apply tile offsets --------------------------------
__global__ void scanC_kernel(int E2) {
    int gid = blockIdx.x * blockDim.x + threadIdx.x;
    int i4 = gid * 4;
    if (gid == 0) {
        int tot = E2;
        #pragma unroll
        for (int j = 0; j < SCAN_NB; j++) tot += g_bsum[j];
        g_ptr[N_NODES] = tot;              // == E
    }
    if (i4 >= N_ITEMS) return;
    int tile = i4 / SCAN_TILE;
    int off = E2;
    for (int j = 0; j < tile; j++) off += g_bsum[j];
    int lim = N_ITEMS - i4;
    int* p = &g_ptr[N_USERS + i4];
    #pragma unroll
    for (int k = 0; k < 4; k++) {
        if (k < lim) {
            int val = p[k] + off;
            p[k] = val;
            g_wcur[i4 + k] = val;
        }
    }
}

// ---------------- step 3: scatter item-half edges + scaled fp16 convert -----
// scatter: 4 edges per thread (vectorized reads); payload from rows + hot g_edge.
// convert: t0[n] = rsqrt(deg(n)) * embeds[n].
__global__ void scatter_convert_kernel(const int* __restrict__ rows,
                                       const float* __restrict__ embeds,
                                       int E2) {
    int idx = blockIdx.x * blockDim.x + threadIdx.x;
    int E2q = (E2 + 3) >> 2;               // scatter thread count

    if (idx < E2q) {
        int base = idx * 4;
        if (base + 3 < E2) {
            int4 cv = *(const int4*)&g_edge[base];   // item node ids
            int4 rv = *(const int4*)&rows[base];     // user ids
            int p0 = atomicAdd(&g_wcur[cv.x - N_USERS], 1);
            int p1 = atomicAdd(&g_wcur[cv.y - N_USERS], 1);
            int p2 = atomicAdd(&g_wcur[cv.z - N_USERS], 1);
            int p3 = atomicAdd(&g_wcur[cv.w - N_USERS], 1);
            g_edge[p0] = rv.x;
            g_edge[p1] = rv.y;
            g_edge[p2] = rv.z;
            g_edge[p3] = rv.w;
        } else {
            for (int k = base; k < E2; k++) {
                int c = g_edge[k];
                int p = atomicAdd(&g_wcur[c - N_USERS], 1);
                g_edge[p] = rows[k];
            }
        }
    }

    int cidx = idx - E2q;
    if (cidx >= 0 && cidx < N_NODES * DH4) {
        int node = cidx >> 3;
        int deg  = g_ptr[node + 1] - g_ptr[node];
        float inv = (deg > 0) ? rsqrtf((float)deg) : 0.f;
        const float4* e4 = (const float4*)embeds;
        float4 f0 = e4[2 * cidx];
        float4 f1 = e4[2 * cidx + 1];
        __half2 h0 = __floats2half2_rn(inv * f0.x, inv * f0.y);
        __half2 h1 = __floats2half2_rn(inv * f0.z, inv * f0.w);
        __half2 h2 = __floats2half2_rn(inv * f1.x, inv * f1.y);
        __half2 h3 = __floats2half2_rn(inv * f1.z, inv * f1.w);
        uint4 u;
        u.x = *(const unsigned*)&h0;
        u.y = *(const unsigned*)&h1;
        u.z = *(const unsigned*)&h2;
        u.w = *(const unsigned*)&h3;
        g_t0[cidx] = u;
    }
}

// ---------------- SpMM helpers -----------------------------------------------
__device__ __forceinline__ void add8(float* s, uint4 x) {
    float2 f0 = __half22float2(*(const __half2*)&x.x);
    float2 f1 = __half22float2(*(const __half2*)&x.y);
    float2 f2 = __half22float2(*(const __half2*)&x.z);
    float2 f3 = __half22float2(*(const __half2*)&x.w);
    s[0] += f0.x; s[1] += f0.y;
    s[2] += f1.x; s[3] += f1.y;
    s[4] += f2.x; s[5] += f2.y;
    s[6] += f3.x; s[7] += f3.y;
}

__device__ __forceinline__ uint4 pack8s(const float* s, float w) {
    __half2 h0 = __floats2half2_rn(w * s[0], w * s[1]);
    __half2 h1 = __floats2half2_rn(w * s[2], w * s[3]);
    __half2 h2 = __floats2half2_rn(w * s[4], w * s[5]);
    __half2 h3 = __floats2half2_rn(w * s[6], w * s[7]);
    uint4 u;
    u.x = *(const unsigned*)&h0;
    u.y = *(const unsigned*)&h1;
    u.z = *(const unsigned*)&h2;
    u.w = *(const unsigned*)&h3;
    return u;
}

// ---------------- SpMM: t_{k+1}[n] = (sum_{c in N(n)} t_k[c]) / deg(n) ------
// 8 lanes per destination node; lane owns one uint4 (8 halves) of the row.
template <int LAYER>   // 0: t0 -> t1,  1: t1 -> t2
__global__ void spmm_kernel() {
    int node = (blockIdx.x * blockDim.x + threadIdx.x) >> 3;
    int ln   = threadIdx.x & 7;
    if (node >= N_NODES) return;

    const uint4* __restrict__ src = (LAYER == 0) ? g_t0 : g_t1;
    uint4* __restrict__ dst       = (LAYER == 0) ? g_t1 : g_t2;

    int beg = g_ptr[node];
    int end = g_ptr[node + 1];

    float s[8] = {0.f, 0.f, 0.f, 0.f, 0.f, 0.f, 0.f, 0.f};
    int e = beg;
    for (; e + 3 < end; e += 4) {
        int a = g_edge[e];
        int b = g_edge[e + 1];
        int c = g_edge[e + 2];
        int d = g_edge[e + 3];
        uint4 xa = src[(size_t)a * DH4 + ln];
        uint4 xb = src[(size_t)b * DH4 + ln];
        uint4 xc = src[(size_t)c * DH4 + ln];
        uint4 xd = src[(size_t)d * DH4 + ln];
        add8(s, xa); add8(s, xb); add8(s, xc); add8(s, xd);
    }
    for (; e < end; e++) {
        uint4 xa = src[(size_t)g_edge[e] * DH4 + ln];
        add8(s, xa);
    }

    int deg = end - beg;
    float w = (deg > 0) ? (1.f / (float)deg) : 0.f;
    dst[(size_t)node * DH4 + ln] = pack8s(s, w);
}

// ---------------- fused layer-3 SpMM + final gather -------------------------
// out = 0.25 * ( emb[n] + (t1[n]+t2[n])*sqrt(deg) + rsqrt(deg)*sum_c t2[c] )
__global__ void final_kernel(const float* __restrict__ embeds,
                             const int* __restrict__ users,
                             const int* __restrict__ pos,
                             const int* __restrict__ neg,
                             float4* __restrict__ out, int B) {
    int row = (blockIdx.x * blockDim.x + threadIdx.x) >> 3;
    int ln  = threadIdx.x & 7;
    if (row >= 3 * B) return;
    int grp = row / B;
    int r   = row - grp * B;
    int n;
    if (grp == 0)      n = users[r];
    else if (grp == 1) n = pos[r] + N_USERS;
    else               n = neg[r] + N_USERS;

    int beg = g_ptr[n];
    int end = g_ptr[n + 1];
    float s[8] = {0.f, 0.f, 0.f, 0.f, 0.f, 0.f, 0.f, 0.f};
    int e = beg;
    for (; e + 3 < end; e += 4) {
        int a = g_edge[e];
        int b = g_edge[e + 1];
        int c = g_edge[e + 2];
        int d = g_edge[e + 3];
        uint4 xa = g_t2[(size_t)a * DH4 + ln];
        uint4 xb = g_t2[(size_t)b * DH4 + ln];
        uint4 xc = g_t2[(size_t)c * DH4 + ln];
        uint4 xd = g_t2[(size_t)d * DH4 + ln];
        add8(s, xa); add8(s, xb); add8(s, xc); add8(s, xd);
    }
    for (; e < end; e++) {
        uint4 xa = g_t2[(size_t)g_edge[e] * DH4 + ln];
        add8(s, xa);
    }

    int deg = end - beg;
    float sq  = (deg > 0) ? sqrtf((float)deg)  : 0.f;
    float inv = (deg > 0) ? rsqrtf((float)deg) : 0.f;

    size_t ni = (size_t)n * DH4 + ln;
    const float4* e4 = (const float4*)embeds;
    float4 f0 = e4[2 * ni];
    float4 f1 = e4[2 * ni + 1];
    uint4 u1 = g_t1[ni];
    uint4 u2 = g_t2[ni];

    float tf[8];
    {
        float2 a0 = __half22float2(*(const __half2*)&u1.x);
        float2 a1 = __half22float2(*(const __half2*)&u1.y);
        float2 a2 = __half22float2(*(const __half2*)&u1.z);
        float2 a3 = __half22float2(*(const __half2*)&u1.w);
        float2 b0 = __half22float2(*(const __half2*)&u2.x);
        float2 b1 = __half22float2(*(const __half2*)&u2.y);
        float2 b2 = __half22float2(*(const __half2*)&u2.z);
        float2 b3 = __half22float2(*(const __half2*)&u2.w);
        tf[0] = a0.x + b0.x; tf[1] = a0.y + b0.y;
        tf[2] = a1.x + b1.x; tf[3] = a1.y + b1.y;
        tf[4] = a2.x + b2.x; tf[5] = a2.y + b2.y;
        tf[6] = a3.x + b3.x; tf[7] = a3.y + b3.y;
    }

    float4 o0, o1;
    o0.x = 0.25f * (f0.x + tf[0] * sq + s[0] * inv);
    o0.y = 0.25f * (f0.y + tf[1] * sq + s[1] * inv);
    o0.z = 0.25f * (f0.z + tf[2] * sq + s[2] * inv);
    o0.w = 0.25f * (f0.w + tf[3] * sq + s[3] * inv);
    o1.x = 0.25f * (f1.x + tf[4] * sq + s[4] * inv);
    o1.y = 0.25f * (f1.y + tf[5] * sq + s[5] * inv);
    o1.z = 0.25f * (f1.z + tf[6] * sq + s[6] * inv);
    o1.w = 0.25f * (f1.w + tf[7] * sq + s[7] * inv);
    size_t oi = (size_t)row * DH4 + ln;
    out[2 * oi]     = o0;
    out[2 * oi + 1] = o1;
}

// ---------------- launch -----------------------------------------------------
extern "C" void kernel_launch(void* const* d_in, const int* in_sizes, int n_in,
                              void* d_out, int out_size) {
    const float* embeds = (const float*)d_in[0];
    const int*   rows   = (const int*)d_in[2];
    const int*   cols   = (const int*)d_in[3];
    const int*   users  = (const int*)d_in[4];
    const int*   pos    = (const int*)d_in[5];
    const int*   neg    = (const int*)d_in[6];
    const int E  = in_sizes[1];
    const int E2 = E >> 1;
    const int B  = in_sizes[4];
    float4* out = (float4*)d_out;

    build1_kernel<<<(E2 + 255) / 256, 256>>>(rows, cols, E2);
    scanA_kernel<<<SCAN_NB, SCAN_BLK>>>();
    scanC_kernel<<<(N_ITEMS / 4 + 256) / 256, 256>>>(E2);

    int E2q = (E2 + 3) >> 2;
    int sc_threads = E2q + N_NODES * DH4;
    scatter_convert_kernel<<<(sc_threads + 255) / 256, 256>>>(rows, embeds, E2);

    const int spmm_blocks = (N_NODES * 8 + 255) / 256;
    spmm_kernel<0><<<spmm_blocks, 256>>>();
    spmm_kernel<1><<<spmm_blocks, 256>>>();

    final_kernel<<<(3 * B * 8 + 255) / 256, 256>>>(embeds, users, pos, neg, out, B);
}